// round 15
// baseline (speedup 1.0000x reference)
#include <cuda_runtime.h>
#include <cstdint>

#define BB 65536
#define HH 1024
#define II 1024
#define EE 16
#define TM 128
#define TN 256
#define TK 32
#define KT (HH / TK)            // 32 k-tiles
#define NSTAGE 4
#define NT (II / TN)            // 4 n-tiles
#define MAXT (BB / TM + EE)     // 528 m-tiles max
#define AROW 144                // padded row: 36 floats (conflict-free frags)
#define BROW 144
#define ASTAGE (TM * AROW)      // 18432 B
#define BSTAGE (TN * BROW)      // 36864 B
#define STAGEB (ASTAGE + BSTAGE)
#define SMEM_GEMM (512 + NSTAGE * STAGEB)
#define NGATE 2048              // gate blocks (32 tokens each, 512 threads)
#define NPERM 256

// ---------------- scratch (device globals; no allocations allowed) ----------
__device__ float    g_wer[(size_t)EE * II * HH];    // tf32-rounded We
__device__ int      g_eidx[BB];
__device__ int      g_perm[BB];
__device__ int      g_bcnt[NGATE * EE];
__device__ int      g_pbase[NPERM * EE];
__device__ int      g_offsets[EE + 1];
__device__ unsigned g_done;
__device__ int4     g_meta[MAXT];                    // (expert, row0, rows, 0)

// ---------------- PTX helpers (sm_80-baseline only) -------------------------
__device__ __forceinline__ uint32_t smem_u32(const void* p) {
    uint32_t a;
    asm("{ .reg .u64 t; cvta.to.shared.u64 t, %1; cvt.u32.u64 %0, t; }"
        : "=r"(a) : "l"(p));
    return a;
}
#define CP_ASYNC16(dst, src) \
    asm volatile("cp.async.cg.shared.global [%0], [%1], 16;" \
                 :: "r"(dst), "l"(src) : "memory")
#define CP_COMMIT() asm volatile("cp.async.commit_group;" ::: "memory")
#define CP_WAIT(n)  asm volatile("cp.async.wait_group %0;" :: "n"(n) : "memory")

__device__ __forceinline__ float lds_f32(uint32_t a) {
    float v;
    asm volatile("ld.shared.b32 %0, [%1];" : "=f"(v) : "r"(a));
    return v;
}
__device__ __forceinline__ uint32_t lds_u32(uint32_t a) {
    uint32_t v;
    asm volatile("ld.shared.b32 %0, [%1];" : "=r"(v) : "r"(a));
    return v;
}
__device__ __forceinline__ uint32_t rna_tf32_bits(float f) {
    uint32_t u;
    asm("cvt.rna.tf32.f32 %0, %1;" : "=r"(u) : "f"(f));
    return u;
}
__device__ __forceinline__ float rna_tf32(float f) {
    return __uint_as_float(rna_tf32_bits(f));
}
__device__ __forceinline__ void mma_tf32(float* d, const uint32_t* a, const uint32_t* b) {
    asm volatile(
        "mma.sync.aligned.m16n8k8.row.col.f32.tf32.tf32.f32 "
        "{%0,%1,%2,%3}, {%4,%5,%6,%7}, {%8,%9}, {%0,%1,%2,%3};"
        : "+f"(d[0]), "+f"(d[1]), "+f"(d[2]), "+f"(d[3])
        : "r"(a[0]), "r"(a[1]), "r"(a[2]), "r"(a[3]), "r"(b[0]), "r"(b[1]));
}

// ---------------- kernel 0: gate + fused scan (last-block pattern) ----------
// 512 threads, 2 tokens/warp, __launch_bounds__(512, 2): ~60 regs -> 2 blocks
// per SM (32 warps) for latency hiding. Quad static prefetch. Per-token fmaf
// chain stays i-ascending with identical operands => scores bitwise-identical
// => identical routing.
__global__ void __launch_bounds__(512, 2) k_gate(const float* __restrict__ x,
                                                 const float* __restrict__ Wg) {
    extern __shared__ float swg[];
    int* shist = reinterpret_cast<int*>(swg + EE * HH);
    int* sflag = shist + EE;
    int tid = threadIdx.x;
    for (int i = tid; i < EE * HH; i += 512) swg[i] = Wg[i];
    if (tid < EE) shist[tid] = 0;
    __syncthreads();

    int warp = tid >> 5, lane = tid & 31;
    int b0 = (blockIdx.x * 16 + warp) * 2;         // 2 tokens per warp
    const float* xp = x + lane;

    float acc[2][EE];
#pragma unroll
    for (int t = 0; t < 2; t++)
#pragma unroll
        for (int e = 0; e < EE; e++) acc[t][e] = 0.f;

    float xv0[2], xv1[2], xv2[2], xv3[2];
    auto ldx = [&](float* b, int idx) {
        int i2 = idx < 31 ? idx : 31;              // clamp: value unused past end
#pragma unroll
        for (int t = 0; t < 2; t++)
            b[t] = xp[(size_t)(b0 + t) * HH + i2 * 32];
    };
    auto fmab = [&](const float* b, int i) {
#pragma unroll
        for (int e = 0; e < EE; e++) {
            float wv = swg[e * HH + i * 32 + lane];
#pragma unroll
            for (int t = 0; t < 2; t++) acc[t][e] = fmaf(b[t], wv, acc[t][e]);
        }
    };

    ldx(xv0, 0); ldx(xv1, 1); ldx(xv2, 2);
    for (int i = 0; i < HH / 32; i += 4) {
        ldx(xv3, i + 3);
        fmab(xv0, i);
        ldx(xv0, i + 4);
        fmab(xv1, i + 1);
        ldx(xv1, i + 5);
        fmab(xv2, i + 2);
        ldx(xv2, i + 6);
        fmab(xv3, i + 3);
    }

#pragma unroll
    for (int t = 0; t < 2; t++) {
#pragma unroll
        for (int e = 0; e < EE; e++) {
            float v = acc[t][e];
            v += __shfl_xor_sync(0xffffffffu, v, 16);
            v += __shfl_xor_sync(0xffffffffu, v, 8);
            v += __shfl_xor_sync(0xffffffffu, v, 4);
            v += __shfl_xor_sync(0xffffffffu, v, 2);
            v += __shfl_xor_sync(0xffffffffu, v, 1);
            acc[t][e] = v;
        }
        if (lane == 0) {
            int be = 0; float bs = acc[t][0];
#pragma unroll
            for (int e = 1; e < EE; e++)
                if (acc[t][e] > bs) { bs = acc[t][e]; be = e; }
            g_eidx[b0 + t] = be;
            atomicAdd(&shist[be], 1);
        }
    }
    __syncthreads();
    if (tid < EE) g_bcnt[blockIdx.x * EE + tid] = shist[tid];
    __threadfence();
    if (tid == 0) {
        unsigned ticket = atomicAdd(&g_done, 1u) + 1u;
        sflag[0] = (ticket == (unsigned)gridDim.x);
    }
    __syncthreads();
    if (!sflag[0]) return;

    // ----- last block: expert totals, offsets, tile metadata, perm bases ----
    if (tid < EE) {
        int run = 0;
        for (int b = 0; b < NGATE; b++) run += g_bcnt[b * EE + tid];
        shist[tid] = run;
    }
    __syncthreads();
    if (tid == 0) {
        int off = 0;
        for (int e = 0; e < EE; e++) { g_offsets[e] = off; off += shist[e]; }
        g_offsets[EE] = off;
        int t = 0;
        for (int e = 0; e < EE; e++) {
            int c = shist[e], r0 = g_offsets[e];
            for (int r = 0; r < c; r += TM) {
                int rows = c - r; if (rows > TM) rows = TM;
                g_meta[t++] = make_int4(e, r0 + r, rows, 0);
            }
        }
        for (; t < MAXT; t++) g_meta[t] = make_int4(0, 0, 0, 0);
        g_done = 0;
    }
    __syncthreads();
    if (tid < EE) {
        // gate block = 32 tokens; perm block = 256 tokens = 8 gate blocks
        int run = g_offsets[tid];
        for (int b = 0; b < NGATE; b++) {
            if ((b & 7) == 0) g_pbase[(b >> 3) * EE + tid] = run;
            run += g_bcnt[b * EE + tid];
        }
    }
}

// ---------------- kernel 1: permutation ------------------------------------
__global__ void __launch_bounds__(256) k_perm() {
    __shared__ int scur[EE];
    int tid = threadIdx.x;
    if (tid < EE) scur[tid] = g_pbase[blockIdx.x * EE + tid];
    __syncthreads();
    int token = blockIdx.x * 256 + tid;
    int e = g_eidx[token];
    int pos = atomicAdd(&scur[e], 1);
    g_perm[pos] = token;
}

// ---------------- kernel 2: We tf32 pre-round (runs on side stream) ---------
__global__ void __launch_bounds__(256) k_rwe(const float4* __restrict__ we) {
    size_t i = (size_t)blockIdx.x * 256 + threadIdx.x;
    float4 v = we[i];
    v.x = rna_tf32(v.x); v.y = rna_tf32(v.y);
    v.z = rna_tf32(v.z); v.w = rna_tf32(v.w);
    reinterpret_cast<float4*>(g_wer)[i] = v;
}

// ---------------- kernel 3: grouped GEMM (R4/R13 exact, measured 841us) -----
// CTA 128x256, 8 warps (2M x 4N), warp tile 64x64, m16n8k8 tf32.
// 4-stage cp.async, one barrier per k-tile, register double-buffered frags.
// This mainloop is AT the mma.sync tf32 pipe floor (6 variants, all 837-875);
// do not modify.
__global__ void __launch_bounds__(256, 1) k_gemm(const float* __restrict__ x,
                                                 float* __restrict__ out) {
    extern __shared__ char smem[];
    int4 meta = g_meta[blockIdx.y];
    int rows = meta.z;
    if (rows == 0) return;
    int e = meta.x, row0 = meta.y;
    int n0 = blockIdx.x * TN;

    int* sperm = reinterpret_cast<int*>(smem);
    uint32_t sbase = smem_u32(smem);
    uint32_t atiles = sbase + 512;
    uint32_t btiles = atiles + ASTAGE;

    int tid = threadIdx.x, wid = tid >> 5, lane = tid & 31;
    int g = lane >> 2, c = lane & 3;
    int wm = wid >> 2, wn = wid & 3;

    if (tid < TM) {
        int r = tid < rows ? tid : (rows - 1);
        sperm[tid] = g_perm[row0 + r];
    }
    __syncthreads();

    int crow = tid >> 3, cck = tid & 7;
    const char* asrc[4];
#pragma unroll
    for (int j = 0; j < 4; j++)
        asrc[j] = reinterpret_cast<const char*>(x) +
                  (size_t)sperm[crow + 32 * j] * (HH * 4) + cck * 16;
    const char* bsrc0 = reinterpret_cast<const char*>(g_wer) +
                        ((size_t)e * II + n0 + crow) * (HH * 4) + cck * 16;
    uint32_t adst0 = atiles + crow * AROW + cck * 16;
    uint32_t bdst0 = btiles + crow * BROW + cck * 16;

    float acc[4][8][4];
#pragma unroll
    for (int mi = 0; mi < 4; mi++)
#pragma unroll
        for (int ni = 0; ni < 8; ni++)
#pragma unroll
            for (int r = 0; r < 4; r++) acc[mi][ni][r] = 0.f;

#pragma unroll
    for (int s = 0; s < NSTAGE - 1; s++) {
        uint32_t so = (uint32_t)s * STAGEB;
#pragma unroll
        for (int j = 0; j < 4; j++)
            CP_ASYNC16(adst0 + so + j * (32 * AROW), asrc[j] + s * 128);
#pragma unroll
        for (int j = 0; j < 8; j++)
            CP_ASYNC16(bdst0 + so + j * (32 * BROW),
                       bsrc0 + (size_t)j * 32 * HH * 4 + s * 128);
        CP_COMMIT();
    }

    uint32_t abase = atiles + (wm * 64 + g) * AROW + c * 4;
    uint32_t bbase = btiles + (wn * 64 + g) * BROW + c * 4;

    uint32_t Ar[2][4][4], Br[2][8][2];

    auto load_frags = [&](uint32_t ab, uint32_t bb, int kk, int buf) {
#pragma unroll
        for (int mi = 0; mi < 4; mi++) {
            uint32_t a0 = ab + mi * (16 * AROW) + kk * 32;
            Ar[buf][mi][0] = rna_tf32_bits(lds_f32(a0));
            Ar[buf][mi][1] = rna_tf32_bits(lds_f32(a0 + 8 * AROW));
            Ar[buf][mi][2] = rna_tf32_bits(lds_f32(a0 + 16));
            Ar[buf][mi][3] = rna_tf32_bits(lds_f32(a0 + 8 * AROW + 16));
        }
#pragma unroll
        for (int ni = 0; ni < 8; ni++) {
            uint32_t b0 = bb + ni * (8 * BROW) + kk * 32;
            Br[buf][ni][0] = lds_u32(b0);
            Br[buf][ni][1] = lds_u32(b0 + 16);
        }
    };

    for (int kt = 0; kt < KT; kt++) {
        CP_WAIT(NSTAGE - 2);
        __syncthreads();

        int pf = kt + NSTAGE - 1;
        if (pf < KT) {
            uint32_t so = (uint32_t)(pf % NSTAGE) * STAGEB;
#pragma unroll
            for (int j = 0; j < 4; j++)
                CP_ASYNC16(adst0 + so + j * (32 * AROW), asrc[j] + pf * 128);
#pragma unroll
            for (int j = 0; j < 8; j++)
                CP_ASYNC16(bdst0 + so + j * (32 * BROW),
                           bsrc0 + (size_t)j * 32 * HH * 4 + pf * 128);
        }
        CP_COMMIT();

        uint32_t so = (uint32_t)(kt % NSTAGE) * STAGEB;
        uint32_t ab = abase + so, bb = bbase + so;

        load_frags(ab, bb, 0, 0);
#pragma unroll
        for (int kk = 0; kk < 4; kk++) {
            if (kk < 3) load_frags(ab, bb, kk + 1, (kk + 1) & 1);
            int buf = kk & 1;
#pragma unroll
            for (int mi = 0; mi < 4; mi++)
#pragma unroll
                for (int ni = 0; ni < 8; ni++)
                    mma_tf32(acc[mi][ni], Ar[buf][mi], Br[buf][ni]);
        }
    }

#pragma unroll
    for (int mi = 0; mi < 4; mi++) {
        int lr0 = wm * 64 + mi * 16 + g;
        int lr1 = lr0 + 8;
        int tok0 = sperm[lr0], tok1 = sperm[lr1];
        float* o0 = out + (size_t)tok0 * II + n0 + wn * 64;
        float* o1 = out + (size_t)tok1 * II + n0 + wn * 64;
        bool v0 = lr0 < rows, v1 = lr1 < rows;
#pragma unroll
        for (int ni = 0; ni < 8; ni++) {
            int nc = ni * 8 + 2 * c;
            if (v0) *reinterpret_cast<float2*>(o0 + nc) =
                make_float2(acc[mi][ni][0], acc[mi][ni][1]);
            if (v1) *reinterpret_cast<float2*>(o1 + nc) =
                make_float2(acc[mi][ni][2], acc[mi][ni][3]);
        }
    }
}

// ---------------- host -------------------------------------------------------
// k_rwe forked onto a side stream (graph-capture-legal event fork/join) so its
// ~35us hides under k_gate (measured-good R11-R13).
extern "C" void kernel_launch(void* const* d_in, const int* in_sizes, int n_in,
                              void* d_out, int out_size) {
    const float* x  = (const float*)d_in[0];
    const float* Wg = (const float*)d_in[1];
    const float* We = (const float*)d_in[2];
    float* out = (float*)d_out;
    (void)in_sizes; (void)n_in; (void)out_size;

    static cudaStream_t s2 = nullptr;
    static cudaEvent_t ev_fork = nullptr, ev_join = nullptr;
    if (s2 == nullptr) {
        cudaStreamCreateWithFlags(&s2, cudaStreamNonBlocking);
        cudaEventCreateWithFlags(&ev_fork, cudaEventDisableTiming);
        cudaEventCreateWithFlags(&ev_join, cudaEventDisableTiming);
        cudaFuncSetAttribute(k_gate, cudaFuncAttributeMaxDynamicSharedMemorySize,
                             EE * HH * 4 + 128);
        cudaFuncSetAttribute(k_gemm, cudaFuncAttributeMaxDynamicSharedMemorySize,
                             SMEM_GEMM);
    }

    cudaEventRecord(ev_fork, 0);
    cudaStreamWaitEvent(s2, ev_fork, 0);
    k_rwe<<<(EE * II * HH / 4) / 256, 256, 0, s2>>>((const float4*)We);
    cudaEventRecord(ev_join, s2);

    k_gate<<<NGATE, 512, EE * HH * 4 + 128>>>(x, Wg);
    k_perm<<<NPERM, 256>>>();

    cudaStreamWaitEvent(0, ev_join, 0);
    k_gemm<<<dim3(NT, MAXT), 256, SMEM_GEMM>>>(x, out);
}

// round 16
// speedup vs baseline: 1.0686x; 1.0686x over previous
#include <cuda_runtime.h>
#include <cstdint>

#define BB 65536
#define HH 1024
#define II 1024
#define EE 16
#define TM 128
#define TN 256
#define TK 32
#define KT (HH / TK)            // 32 k-tiles
#define NSTAGE 4
#define NT (II / TN)            // 4 n-tiles
#define MAXT (BB / TM + EE)     // 528 m-tiles max
#define AROW 144                // padded row: 36 floats (conflict-free frags)
#define BROW 144
#define ASTAGE (TM * AROW)      // 18432 B
#define BSTAGE (TN * BROW)      // 36864 B
#define STAGEB (ASTAGE + BSTAGE)
#define SMEM_GEMM (512 + NSTAGE * STAGEB)
#define NGATE 1024              // gate blocks (64 tokens each, 512 threads)
#define NPERM 256

// ---------------- scratch (device globals; no allocations allowed) ----------
__device__ float    g_wer[(size_t)EE * II * HH];    // tf32-rounded We
__device__ int      g_eidx[BB];
__device__ int      g_perm[BB];
__device__ int      g_bcnt[NGATE * EE];
__device__ int      g_pbase[NPERM * EE];
__device__ int      g_offsets[EE + 1];
__device__ unsigned g_done;
__device__ int4     g_meta[MAXT];                    // (expert, row0, rows, 0)

// ---------------- PTX helpers (sm_80-baseline only) -------------------------
__device__ __forceinline__ uint32_t smem_u32(const void* p) {
    uint32_t a;
    asm("{ .reg .u64 t; cvta.to.shared.u64 t, %1; cvt.u32.u64 %0, t; }"
        : "=r"(a) : "l"(p));
    return a;
}
#define CP_ASYNC16(dst, src) \
    asm volatile("cp.async.cg.shared.global [%0], [%1], 16;" \
                 :: "r"(dst), "l"(src) : "memory")
#define CP_COMMIT() asm volatile("cp.async.commit_group;" ::: "memory")
#define CP_WAIT(n)  asm volatile("cp.async.wait_group %0;" :: "n"(n) : "memory")

__device__ __forceinline__ float lds_f32(uint32_t a) {
    float v;
    asm volatile("ld.shared.b32 %0, [%1];" : "=f"(v) : "r"(a));
    return v;
}
__device__ __forceinline__ uint32_t lds_u32(uint32_t a) {
    uint32_t v;
    asm volatile("ld.shared.b32 %0, [%1];" : "=r"(v) : "r"(a));
    return v;
}
__device__ __forceinline__ uint32_t rna_tf32_bits(float f) {
    uint32_t u;
    asm("cvt.rna.tf32.f32 %0, %1;" : "=r"(u) : "f"(f));
    return u;
}
__device__ __forceinline__ float rna_tf32(float f) {
    return __uint_as_float(rna_tf32_bits(f));
}
__device__ __forceinline__ void mma_tf32(float* d, const uint32_t* a, const uint32_t* b) {
    asm volatile(
        "mma.sync.aligned.m16n8k8.row.col.f32.tf32.tf32.f32 "
        "{%0,%1,%2,%3}, {%4,%5,%6,%7}, {%8,%9}, {%0,%1,%2,%3};"
        : "+f"(d[0]), "+f"(d[1]), "+f"(d[2]), "+f"(d[3])
        : "r"(a[0]), "r"(a[1]), "r"(a[2]), "r"(a[3]), "r"(b[0]), "r"(b[1]));
}

// ---------------- kernel 0: gate + fused scan (R13 measured-best) -----------
// 512 threads (16 warps), 4 tokens/warp, ONE shared Wg stage (now staged via
// cp.async: fire-and-forget, hides block-start DRAM latency). Quad static
// prefetch. i-ascending fmaf chain with identical operands => scores
// bitwise-identical => identical routing.
__global__ void __launch_bounds__(512) k_gate(const float* __restrict__ x,
                                              const float* __restrict__ Wg) {
    extern __shared__ float swg[];
    int* shist = reinterpret_cast<int*>(swg + EE * HH);
    int* sflag = shist + EE;
    int tid = threadIdx.x;

    // Wg staging via cp.async: 64KB / 512 threads = 8 x 16B chunks each.
    {
        uint32_t sdst = smem_u32(swg) + tid * 16;
        const char* ssrc = reinterpret_cast<const char*>(Wg) + tid * 16;
#pragma unroll
        for (int j = 0; j < 8; j++)
            CP_ASYNC16(sdst + j * 8192, ssrc + j * 8192);
        CP_COMMIT();
    }
    if (tid < EE) shist[tid] = 0;
    CP_WAIT(0);
    __syncthreads();

    int warp = tid >> 5, lane = tid & 31;
    int b0 = (blockIdx.x * 16 + warp) * 4;
    const float* xp = x + lane;

    float acc[4][EE];
#pragma unroll
    for (int t = 0; t < 4; t++)
#pragma unroll
        for (int e = 0; e < EE; e++) acc[t][e] = 0.f;

    float xv0[4], xv1[4], xv2[4], xv3[4];
    auto ldx = [&](float* b, int idx) {
        int i2 = idx < 31 ? idx : 31;            // clamp: value unused past end
#pragma unroll
        for (int t = 0; t < 4; t++)
            b[t] = xp[(size_t)(b0 + t) * HH + i2 * 32];
    };
    auto fmab = [&](const float* b, int i) {
#pragma unroll
        for (int e = 0; e < EE; e++) {
            float wv = swg[e * HH + i * 32 + lane];
#pragma unroll
            for (int t = 0; t < 4; t++) acc[t][e] = fmaf(b[t], wv, acc[t][e]);
        }
    };

    ldx(xv0, 0); ldx(xv1, 1); ldx(xv2, 2);
    for (int i = 0; i < HH / 32; i += 4) {
        ldx(xv3, i + 3);
        fmab(xv0, i);
        ldx(xv0, i + 4);
        fmab(xv1, i + 1);
        ldx(xv1, i + 5);
        fmab(xv2, i + 2);
        ldx(xv2, i + 6);
        fmab(xv3, i + 3);
    }

#pragma unroll
    for (int t = 0; t < 4; t++) {
#pragma unroll
        for (int e = 0; e < EE; e++) {
            float v = acc[t][e];
            v += __shfl_xor_sync(0xffffffffu, v, 16);
            v += __shfl_xor_sync(0xffffffffu, v, 8);
            v += __shfl_xor_sync(0xffffffffu, v, 4);
            v += __shfl_xor_sync(0xffffffffu, v, 2);
            v += __shfl_xor_sync(0xffffffffu, v, 1);
            acc[t][e] = v;
        }
        if (lane == 0) {
            int be = 0; float bs = acc[t][0];
#pragma unroll
            for (int e = 1; e < EE; e++)
                if (acc[t][e] > bs) { bs = acc[t][e]; be = e; }
            g_eidx[b0 + t] = be;
            atomicAdd(&shist[be], 1);
        }
    }
    __syncthreads();
    if (tid < EE) g_bcnt[blockIdx.x * EE + tid] = shist[tid];
    __threadfence();
    if (tid == 0) {
        unsigned ticket = atomicAdd(&g_done, 1u) + 1u;
        sflag[0] = (ticket == (unsigned)gridDim.x);
    }
    __syncthreads();
    if (!sflag[0]) return;

    // ----- last block: expert totals, offsets, tile metadata, perm bases ----
    if (tid < EE) {
        int run = 0;
        for (int b = 0; b < NGATE; b++) run += g_bcnt[b * EE + tid];
        shist[tid] = run;
    }
    __syncthreads();
    if (tid == 0) {
        int off = 0;
        for (int e = 0; e < EE; e++) { g_offsets[e] = off; off += shist[e]; }
        g_offsets[EE] = off;
        int t = 0;
        for (int e = 0; e < EE; e++) {
            int c = shist[e], r0 = g_offsets[e];
            for (int r = 0; r < c; r += TM) {
                int rows = c - r; if (rows > TM) rows = TM;
                g_meta[t++] = make_int4(e, r0 + r, rows, 0);
            }
        }
        for (; t < MAXT; t++) g_meta[t] = make_int4(0, 0, 0, 0);
        g_done = 0;
    }
    __syncthreads();
    if (tid < EE) {
        // gate block = 64 tokens; perm block = 256 tokens = 4 gate blocks
        int run = g_offsets[tid];
        for (int b = 0; b < NGATE; b++) {
            if ((b & 3) == 0) g_pbase[(b >> 2) * EE + tid] = run;
            run += g_bcnt[b * EE + tid];
        }
    }
}

// ---------------- kernel 1: permutation ------------------------------------
__global__ void __launch_bounds__(256) k_perm() {
    __shared__ int scur[EE];
    int tid = threadIdx.x;
    if (tid < EE) scur[tid] = g_pbase[blockIdx.x * EE + tid];
    __syncthreads();
    int token = blockIdx.x * 256 + tid;
    int e = g_eidx[token];
    int pos = atomicAdd(&scur[e], 1);
    g_perm[pos] = token;
}

// ---------------- kernel 2: We tf32 pre-round (runs on side stream) ---------
__global__ void __launch_bounds__(256) k_rwe(const float4* __restrict__ we) {
    size_t i = (size_t)blockIdx.x * 256 + threadIdx.x;
    float4 v = we[i];
    v.x = rna_tf32(v.x); v.y = rna_tf32(v.y);
    v.z = rna_tf32(v.z); v.w = rna_tf32(v.w);
    reinterpret_cast<float4*>(g_wer)[i] = v;
}

// ---------------- kernel 3: grouped GEMM (R4/R13 exact, measured 837-841) ---
// CTA 128x256, 8 warps (2M x 4N), warp tile 64x64, m16n8k8 tf32.
// 4-stage cp.async, one barrier per k-tile, register double-buffered frags.
// At the mma.sync tf32 issue floor (7 variants, all 837-875): do not modify.
__global__ void __launch_bounds__(256, 1) k_gemm(const float* __restrict__ x,
                                                 float* __restrict__ out) {
    extern __shared__ char smem[];
    int4 meta = g_meta[blockIdx.y];
    int rows = meta.z;
    if (rows == 0) return;
    int e = meta.x, row0 = meta.y;
    int n0 = blockIdx.x * TN;

    int* sperm = reinterpret_cast<int*>(smem);
    uint32_t sbase = smem_u32(smem);
    uint32_t atiles = sbase + 512;
    uint32_t btiles = atiles + ASTAGE;

    int tid = threadIdx.x, wid = tid >> 5, lane = tid & 31;
    int g = lane >> 2, c = lane & 3;
    int wm = wid >> 2, wn = wid & 3;

    if (tid < TM) {
        int r = tid < rows ? tid : (rows - 1);
        sperm[tid] = g_perm[row0 + r];
    }
    __syncthreads();

    int crow = tid >> 3, cck = tid & 7;
    const char* asrc[4];
#pragma unroll
    for (int j = 0; j < 4; j++)
        asrc[j] = reinterpret_cast<const char*>(x) +
                  (size_t)sperm[crow + 32 * j] * (HH * 4) + cck * 16;
    const char* bsrc0 = reinterpret_cast<const char*>(g_wer) +
                        ((size_t)e * II + n0 + crow) * (HH * 4) + cck * 16;
    uint32_t adst0 = atiles + crow * AROW + cck * 16;
    uint32_t bdst0 = btiles + crow * BROW + cck * 16;

    float acc[4][8][4];
#pragma unroll
    for (int mi = 0; mi < 4; mi++)
#pragma unroll
        for (int ni = 0; ni < 8; ni++)
#pragma unroll
            for (int r = 0; r < 4; r++) acc[mi][ni][r] = 0.f;

#pragma unroll
    for (int s = 0; s < NSTAGE - 1; s++) {
        uint32_t so = (uint32_t)s * STAGEB;
#pragma unroll
        for (int j = 0; j < 4; j++)
            CP_ASYNC16(adst0 + so + j * (32 * AROW), asrc[j] + s * 128);
#pragma unroll
        for (int j = 0; j < 8; j++)
            CP_ASYNC16(bdst0 + so + j * (32 * BROW),
                       bsrc0 + (size_t)j * 32 * HH * 4 + s * 128);
        CP_COMMIT();
    }

    uint32_t abase = atiles + (wm * 64 + g) * AROW + c * 4;
    uint32_t bbase = btiles + (wn * 64 + g) * BROW + c * 4;

    uint32_t Ar[2][4][4], Br[2][8][2];

    auto load_frags = [&](uint32_t ab, uint32_t bb, int kk, int buf) {
#pragma unroll
        for (int mi = 0; mi < 4; mi++) {
            uint32_t a0 = ab + mi * (16 * AROW) + kk * 32;
            Ar[buf][mi][0] = rna_tf32_bits(lds_f32(a0));
            Ar[buf][mi][1] = rna_tf32_bits(lds_f32(a0 + 8 * AROW));
            Ar[buf][mi][2] = rna_tf32_bits(lds_f32(a0 + 16));
            Ar[buf][mi][3] = rna_tf32_bits(lds_f32(a0 + 8 * AROW + 16));
        }
#pragma unroll
        for (int ni = 0; ni < 8; ni++) {
            uint32_t b0 = bb + ni * (8 * BROW) + kk * 32;
            Br[buf][ni][0] = lds_u32(b0);
            Br[buf][ni][1] = lds_u32(b0 + 16);
        }
    };

    for (int kt = 0; kt < KT; kt++) {
        CP_WAIT(NSTAGE - 2);
        __syncthreads();

        int pf = kt + NSTAGE - 1;
        if (pf < KT) {
            uint32_t so = (uint32_t)(pf % NSTAGE) * STAGEB;
#pragma unroll
            for (int j = 0; j < 4; j++)
                CP_ASYNC16(adst0 + so + j * (32 * AROW), asrc[j] + pf * 128);
#pragma unroll
            for (int j = 0; j < 8; j++)
                CP_ASYNC16(bdst0 + so + j * (32 * BROW),
                           bsrc0 + (size_t)j * 32 * HH * 4 + pf * 128);
        }
        CP_COMMIT();

        uint32_t so = (uint32_t)(kt % NSTAGE) * STAGEB;
        uint32_t ab = abase + so, bb = bbase + so;

        load_frags(ab, bb, 0, 0);
#pragma unroll
        for (int kk = 0; kk < 4; kk++) {
            if (kk < 3) load_frags(ab, bb, kk + 1, (kk + 1) & 1);
            int buf = kk & 1;
#pragma unroll
            for (int mi = 0; mi < 4; mi++)
#pragma unroll
                for (int ni = 0; ni < 8; ni++)
                    mma_tf32(acc[mi][ni], Ar[buf][mi], Br[buf][ni]);
        }
    }

#pragma unroll
    for (int mi = 0; mi < 4; mi++) {
        int lr0 = wm * 64 + mi * 16 + g;
        int lr1 = lr0 + 8;
        int tok0 = sperm[lr0], tok1 = sperm[lr1];
        float* o0 = out + (size_t)tok0 * II + n0 + wn * 64;
        float* o1 = out + (size_t)tok1 * II + n0 + wn * 64;
        bool v0 = lr0 < rows, v1 = lr1 < rows;
#pragma unroll
        for (int ni = 0; ni < 8; ni++) {
            int nc = ni * 8 + 2 * c;
            if (v0) *reinterpret_cast<float2*>(o0 + nc) =
                make_float2(acc[mi][ni][0], acc[mi][ni][1]);
            if (v1) *reinterpret_cast<float2*>(o1 + nc) =
                make_float2(acc[mi][ni][2], acc[mi][ni][3]);
        }
    }
}

// ---------------- host -------------------------------------------------------
// k_rwe forked onto a side stream (graph-capture-legal event fork/join) so its
// ~35us hides under k_gate (measured-good R11-R13).
extern "C" void kernel_launch(void* const* d_in, const int* in_sizes, int n_in,
                              void* d_out, int out_size) {
    const float* x  = (const float*)d_in[0];
    const float* Wg = (const float*)d_in[1];
    const float* We = (const float*)d_in[2];
    float* out = (float*)d_out;
    (void)in_sizes; (void)n_in; (void)out_size;

    static cudaStream_t s2 = nullptr;
    static cudaEvent_t ev_fork = nullptr, ev_join = nullptr;
    if (s2 == nullptr) {
        cudaStreamCreateWithFlags(&s2, cudaStreamNonBlocking);
        cudaEventCreateWithFlags(&ev_fork, cudaEventDisableTiming);
        cudaEventCreateWithFlags(&ev_join, cudaEventDisableTiming);
        cudaFuncSetAttribute(k_gate, cudaFuncAttributeMaxDynamicSharedMemorySize,
                             EE * HH * 4 + 128);
        cudaFuncSetAttribute(k_gemm, cudaFuncAttributeMaxDynamicSharedMemorySize,
                             SMEM_GEMM);
    }

    cudaEventRecord(ev_fork, 0);
    cudaStreamWaitEvent(s2, ev_fork, 0);
    k_rwe<<<(EE * II * HH / 4) / 256, 256, 0, s2>>>((const float4*)We);
    cudaEventRecord(ev_join, s2);

    k_gate<<<NGATE, 512, EE * HH * 4 + 128>>>(x, Wg);
    k_perm<<<NPERM, 256>>>();

    cudaStreamWaitEvent(0, ev_join, 0);
    k_gemm<<<dim3(NT, MAXT), 256, SMEM_GEMM>>>(x, out);
}